// round 5
// baseline (speedup 1.0000x reference)
#include <cuda_runtime.h>

// QConv1D quantum sim, R5: closed-form (Heisenberg / independent-set transfer
// matrix DP, see R4) fused into a SINGLE kernel.
//  - 8 consecutive lanes = one conv position x 8 out-channels
//  - lane sub-index u = o-channel AND the qubit whose x-trig this lane computes
//  - x trig: one __sincosf per thread, shared via 16 warp shfls
//  - weight trig: 128 precise sincosf per block into smem (tiny, redundant ok)
constexpr int O_CH  = 8;
constexpr int NQ    = 8;
constexpr int L_IN  = 512;
constexpr int L_OUT = 509;
constexpr int B_SZ  = 16;
constexpr int N_POS = B_SZ * L_OUT;          // 8144
constexpr int POS_PER_BLK = 256 / O_CH;      // 32

__global__ __launch_bounds__(256)
void qconv_kernel(const float* __restrict__ x,
                  const float* __restrict__ w,
                  float* __restrict__ out)
{
    __shared__ float4 sw[O_CH * NQ];         // {cos p0, sin p0, cos p1, sin p1}

    const int tid = threadIdx.x;

    // --- weight trig (threads 0..63), w layout (O, NQ, 2): w[o*16 + q*2 + l]
    if (tid < O_CH * NQ) {
        float c0, s0, c1, s1;
        sincosf(w[tid * 2 + 0], &s0, &c0);
        sincosf(w[tid * 2 + 1], &s1, &c1);
        sw[tid] = make_float4(c0, s0, c1, s1);
    }

    // --- this thread's sim: position n, out-channel u
    const int n_raw = blockIdx.x * POS_PER_BLK + (tid >> 3);
    const bool valid = (n_raw < N_POS);
    const int n   = valid ? n_raw : N_POS - 1;
    const int u   = tid & 7;                 // o-channel AND trig qubit
    const int bb  = n / L_OUT;
    const int pos = n - bb * L_OUT;

    // lane u computes x-trig for qubit q=u at this position:
    //   q<4 -> channel 0, offset q ; q>=4 -> channel 1, offset q-4
    const float xv = x[(bb * 2 + (u >> 2)) * L_IN + pos + (u & 3)];
    float sx, cx;
    __sincosf(xv, &sx, &cx);

    __syncthreads();

    const int gbase = (tid & 31) & ~7;       // group base lane within warp
    const float4* __restrict__ wv = sw + u * NQ;

    // --- 3-state transfer-matrix DP over the 8-qubit chain
    float v00 = 1.f, v01 = 1.f, v10 = 0.f;
#pragma unroll
    for (int q = 0; q < NQ; q++) {
        const float cxq = __shfl_sync(0xffffffffu, cx, gbase + q);
        const float sxq = __shfl_sync(0xffffffffu, sx, gbase + q);
        const float4 wq = wv[q];
        // angle addition: C = cos(x+p0), S = sin(x+p0)
        const float C = cxq * wq.x - sxq * wq.y;
        const float S = sxq * wq.x + cxq * wq.y;
        const float uu  = -wq.w * S;               // -sin(p1) sin(x+p0)
        const float n00 = wq.z * fmaf(v00, C, v10);
        const float n01 = wq.z * fmaf(v10, C, v00);
        const float n10 = uu * v01;
        v00 = n00; v01 = n01; v10 = n10;
    }
    const float E = v00 + v10;                     // boundary b_8 = 0

    // --- reference reshape reinterpretation: flat [o][n] read as [b'][p'][o']
    if (valid) {
        const int s  = u * N_POS + n;
        const int oo = s & 7;
        const int tt = s >> 3;
        const int bo = tt / L_OUT;
        const int po = tt - bo * L_OUT;
        out[(bo * O_CH + oo) * L_OUT + po] = E;
    }
}

extern "C" void kernel_launch(void* const* d_in, const int* in_sizes, int n_in,
                              void* d_out, int out_size)
{
    const float* x = (const float*)d_in[0];
    const float* w = (const float*)d_in[1];
    float* out = (float*)d_out;
    const int blocks = (N_POS + POS_PER_BLK - 1) / POS_PER_BLK;   // 255
    qconv_kernel<<<blocks, 256>>>(x, w, out);
}